// round 7
// baseline (speedup 1.0000x reference)
#include <cuda_runtime.h>
#include <cuda_bf16.h>
#include <cstdint>

#define N_NODES 50000
#define N_PAD   50048                  // 391 * 128
#define TILE    128
#define NTILES  391
#define TPB     256

#define A_STRIDE 800                   // A1 row: 96 pairs (768B) + 32B pad
#define A_BYTES  (128 * A_STRIDE)      // 102400 per tile
#define W_STRIDE 96                    // W chunk row: 8 pairs (64B) + 32B pad
#define W_CHUNK  (128 * W_STRIDE)      // 12288
#define SMEM_BYTES (A_BYTES + W_CHUNK) // 114688 -> 2 CTAs/SM

// __device__ scratch (allocation-free rule)
__device__ __align__(16) unsigned char g_Wm[12 * W_CHUNK];              // msg W, k16 chunks
__device__ __align__(16) unsigned char g_Wa[16 * W_CHUNK];              // apply W, k16 chunks
__device__ __align__(16) unsigned char g_A1[(size_t)N_PAD * A_STRIDE];  // packed gather sums
__device__ __align__(16) unsigned char g_An[(size_t)N_PAD * 512];       // packed own rows
__device__ int g_flag[NTILES];                                          // tile-ready flags

__device__ __forceinline__ void add4(float4& a, const float4 b) {
    a.x += b.x; a.y += b.y; a.z += b.z; a.w += b.w;
}
__device__ __forceinline__ void pack2(float a, float b, uint32_t& hw, uint32_t& lw) {
    __nv_bfloat162 h = __floats2bfloat162_rn(a, b);
    hw = *reinterpret_cast<uint32_t*>(&h);
    float2 hf = __bfloat1622float2(h);
    __nv_bfloat162 l = __floats2bfloat162_rn(a - hf.x, b - hf.y);
    lw = *reinterpret_cast<uint32_t*>(&l);
}
__device__ __forceinline__ void mma_bf16(float c[4],
                                         uint32_t a0, uint32_t a1, uint32_t a2, uint32_t a3,
                                         uint32_t b0, uint32_t b1) {
    asm volatile(
        "mma.sync.aligned.m16n8k16.row.col.f32.bf16.bf16.f32 "
        "{%0,%1,%2,%3}, {%4,%5,%6,%7}, {%8,%9}, {%0,%1,%2,%3};"
        : "+f"(c[0]), "+f"(c[1]), "+f"(c[2]), "+f"(c[3])
        : "r"(a0), "r"(a1), "r"(a2), "r"(a3), "r"(b0), "r"(b1));
}

// one-time: weights -> chunked hi/lo pair-interleaved layout; zero tile flags
__global__ void prep_weights(const float* __restrict__ Wm, const float* __restrict__ Wa) {
    int i = blockIdx.x * blockDim.x + threadIdx.x;
    if (i < NTILES) g_flag[i] = 0;
    if (i >= 128 * 256) return;
    int o = i >> 8, k = i & 255;
    {
        float w = Wa[o * 256 + k];
        __nv_bfloat16 h = __float2bfloat16(w);
        __nv_bfloat16 l = __float2bfloat16(w - __bfloat162float(h));
        unsigned char* p = g_Wa + (k >> 4) * W_CHUNK + o * W_STRIDE + ((k >> 1) & 7) * 8 + (k & 1) * 2;
        *(__nv_bfloat16*)p = h;
        *(__nv_bfloat16*)(p + 4) = l;
    }
    if (k < 192) {
        float w = Wm[o * 192 + k];
        __nv_bfloat16 h = __float2bfloat16(w);
        __nv_bfloat16 l = __float2bfloat16(w - __bfloat162float(h));
        unsigned char* p = g_Wm + (k >> 4) * W_CHUNK + o * W_STRIDE + ((k >> 1) & 7) * 8 + (k & 1) * 2;
        *(__nv_bfloat16*)p = h;
        *(__nv_bfloat16*)(p + 4) = l;
    }
}

// One k16-step of the split-bf16 GEMM: warp tile m32 x n64, 48 HMMAs.
__device__ __forceinline__ void mma_kstep(float acc[2][8][4], const char* __restrict__ A,
                                          const char* __restrict__ WB,
                                          int mrow, int nbase, int gid, int tig, int kb) {
    uint2 a[2][4];
#pragma unroll
    for (int s = 0; s < 2; ++s) {
        const char* ar = A + (mrow + s * 16 + gid) * A_STRIDE;
        a[s][0] = *(const uint2*)(ar + (kb + tig) * 8);
        a[s][1] = *(const uint2*)(ar + 8 * A_STRIDE + (kb + tig) * 8);
        a[s][2] = *(const uint2*)(ar + (kb + 4 + tig) * 8);
        a[s][3] = *(const uint2*)(ar + 8 * A_STRIDE + (kb + 4 + tig) * 8);
    }
#pragma unroll
    for (int t = 0; t < 8; ++t) {
        const char* wr = WB + (nbase + t * 8 + gid) * W_STRIDE + tig * 8;
        uint2 B0 = *(const uint2*)(wr);
        uint2 B1 = *(const uint2*)(wr + 32);
#pragma unroll
        for (int s = 0; s < 2; ++s) {
            mma_bf16(acc[s][t], a[s][0].x, a[s][1].x, a[s][2].x, a[s][3].x, B0.x, B1.x);  // hi*hi
            mma_bf16(acc[s][t], a[s][0].x, a[s][1].x, a[s][2].x, a[s][3].x, B0.y, B1.y);  // hi*lo
            mma_bf16(acc[s][t], a[s][0].y, a[s][1].y, a[s][2].y, a[s][3].y, B0.x, B1.x);  // lo*hi
        }
    }
}

__global__ void __launch_bounds__(TPB, 2)
sage_combined(const float* __restrict__ nfeats, const float* __restrict__ efeats,
              const float* __restrict__ b_msg, const float* __restrict__ b_apply,
              const int* __restrict__ src_idx, float* __restrict__ out)
{
    extern __shared__ char sm[];
    const int tid  = threadIdx.x;
    const int wid  = tid >> 5;
    const int lane = tid & 31;
    const int bid  = blockIdx.x;

    if (bid < NTILES) {
        // ================= PRODUCER: gather tile bid (128 nodes) =================
        const float4* nf4 = (const float4*)nfeats;
        const float4* ef4 = (const float4*)efeats;
        for (int q = 0; q < 16; ++q) {
            const int nd = wid * 16 + q;
            const int node = bid * TILE + nd;
            if (node >= N_NODES) break;
            const int myidx = __ldg(src_idx + node * 16 + (lane & 15));
            float4 a0 = {0,0,0,0}, a1 = {0,0,0,0}, ae = {0,0,0,0};
            const float4 own = __ldg(nf4 + (size_t)node * 32 + lane);
#pragma unroll
            for (int j = 0; j < 16; j += 2) {
                const int s0 = __shfl_sync(0xffffffffu, myidx, j);
                const int s1 = __shfl_sync(0xffffffffu, myidx, j + 1);
                add4(a0, __ldg(nf4 + (size_t)s0 * 32 + lane));
                add4(a1, __ldg(nf4 + (size_t)s1 * 32 + lane));
                add4(ae, __ldg(ef4 + ((size_t)node * 16 + j + (lane >> 4)) * 16 + (lane & 15)));
            }
            add4(a0, a1);
            ae.x += __shfl_down_sync(0xffffffffu, ae.x, 16);
            ae.y += __shfl_down_sync(0xffffffffu, ae.y, 16);
            ae.z += __shfl_down_sync(0xffffffffu, ae.z, 16);
            ae.w += __shfl_down_sync(0xffffffffu, ae.w, 16);
            const float inv = 0.0625f;   // mean: exactly 16 in-edges per node
            unsigned char* ar = g_A1 + (size_t)node * A_STRIDE;
            uint32_t h0, l0, h1, l1;
            pack2(a0.x * inv, a0.y * inv, h0, l0);
            pack2(a0.z * inv, a0.w * inv, h1, l1);
            *(uint4*)(ar + lane * 16) = make_uint4(h0, l0, h1, l1);
            if (lane < 16) {
                pack2(ae.x * inv, ae.y * inv, h0, l0);
                pack2(ae.z * inv, ae.w * inv, h1, l1);
                *(uint4*)(ar + 512 + lane * 16) = make_uint4(h0, l0, h1, l1);
            }
            pack2(own.x, own.y, h0, l0);
            pack2(own.z, own.w, h1, l1);
            *(uint4*)(g_An + (size_t)node * 512 + lane * 16) = make_uint4(h0, l0, h1, l1);
        }
        __syncthreads();
        if (tid == 0) {
            __threadfence();
            atomicExch(&g_flag[bid], 1);
        }
        return;
    }

    // ================= CONSUMER: GEMM tile =================
    const int tile = bid - NTILES;
    const int base = tile * TILE;
    char* A  = sm;
    char* WB = sm + A_BYTES;
    const int gid  = lane >> 2;
    const int tig  = lane & 3;
    const int mrow  = (wid & 3) * 32;
    const int nbase = (wid >> 2) * 64;

    // prefetch W_msg chunk 0 while (possibly) waiting for the producer
    uint2 wreg[6];
    uint2* wbs = (uint2*)WB;
    {
        const uint2* g0 = (const uint2*)g_Wm;
#pragma unroll
        for (int i = 0; i < 6; ++i) wreg[i] = __ldg(g0 + tid + i * 256);
    }
    if (tid == 0) {
        unsigned v;
        do {
            asm volatile("ld.acquire.gpu.b32 %0, [%1];" : "=r"(v) : "l"(&g_flag[tile]) : "memory");
            if (!v) __nanosleep(200);
        } while (!v);
    }
    __syncthreads();

    // ---- stage A1 tile: linear copy ----
    {
        const float4* s = (const float4*)(g_A1 + (size_t)tile * A_BYTES);
        float4* d = (float4*)A;
#pragma unroll
        for (int i = 0; i < 25; ++i) d[tid + i * TPB] = s[tid + i * TPB];
    }

    float acc[2][8][4];
#pragma unroll
    for (int s = 0; s < 2; ++s)
#pragma unroll
        for (int t = 0; t < 8; ++t)
#pragma unroll
            for (int j = 0; j < 4; ++j) acc[s][t][j] = 0.f;

    // ---- GEMM1: K=192, chunks 0..11 of g_Wm ----
    for (int kk = 0; kk < 12; ++kk) {
        __syncthreads();
#pragma unroll
        for (int i = 0; i < 6; ++i) wbs[tid + i * 256] = wreg[i];
        if (kk + 1 < 12) {
            const uint2* gn = (const uint2*)(g_Wm + (kk + 1) * W_CHUNK);
#pragma unroll
            for (int i = 0; i < 6; ++i) wreg[i] = __ldg(gn + tid + i * 256);
        }
        __syncthreads();
        mma_kstep(acc, A, WB, mrow, nbase, gid, tig, kk * 8);
    }

    // prefetch W_apply chunk 8 (h-half) while writing h back
    {
        const uint2* gn = (const uint2*)(g_Wa + 8 * W_CHUNK);
#pragma unroll
        for (int i = 0; i < 6; ++i) wreg[i] = __ldg(gn + tid + i * 256);
    }
    // h = D1 + b_msg -> A pairs [0,64). Safe: last kstep reads pairs 88..95 only.
#pragma unroll
    for (int t = 0; t < 8; ++t) {
        const int n0 = nbase + t * 8 + 2 * tig;
        const float2 bm = __ldg((const float2*)(b_msg + n0));
#pragma unroll
        for (int s = 0; s < 2; ++s) {
            char* ar = A + (mrow + s * 16 + gid) * A_STRIDE;
            uint32_t hw, lw;
            pack2(acc[s][t][0] + bm.x, acc[s][t][1] + bm.y, hw, lw);
            *(uint2*)(ar + (n0 >> 1) * 8) = make_uint2(hw, lw);
            pack2(acc[s][t][2] + bm.x, acc[s][t][3] + bm.y, hw, lw);
            *(uint2*)(ar + 8 * A_STRIDE + (n0 >> 1) * 8) = make_uint2(hw, lw);
        }
    }
#pragma unroll
    for (int s = 0; s < 2; ++s)
#pragma unroll
        for (int t = 0; t < 8; ++t)
#pragma unroll
            for (int j = 0; j < 4; ++j) acc[s][t][j] = 0.f;

    // ---- GEMM2a: h x W_apply[:,128:256] (chunks 8..15) ----
    for (int kk = 0; kk < 8; ++kk) {
        __syncthreads();
#pragma unroll
        for (int i = 0; i < 6; ++i) wbs[tid + i * 256] = wreg[i];
        if (kk + 1 < 8) {
            const uint2* gn = (const uint2*)(g_Wa + (9 + kk) * W_CHUNK);
#pragma unroll
            for (int i = 0; i < 6; ++i) wreg[i] = __ldg(gn + tid + i * 256);
        }
        __syncthreads();
        mma_kstep(acc, A, WB, mrow, nbase, gid, tig, kk * 8);
    }

    // prefetch W_apply chunk 0
    {
        const uint2* gn = (const uint2*)(g_Wa);
#pragma unroll
        for (int i = 0; i < 6; ++i) wreg[i] = __ldg(gn + tid + i * 256);
    }
    __syncthreads();    // all GEMM2a reads of A done before restage

    // ---- restage packed own-feature rows -> A pairs [0,64) ----
    {
        const float4* s = (const float4*)(g_An + (size_t)base * 512);
#pragma unroll
        for (int i = 0; i < 16; ++i) {
            const int idx = tid + i * TPB;
            const int row = idx >> 5, col = idx & 31;
            *(float4*)(A + row * A_STRIDE + col * 16) = s[idx];
        }
    }

    // ---- GEMM2b: nfeats x W_apply[:,0:128] (chunks 0..7), accumulate ----
    for (int kk = 0; kk < 8; ++kk) {
        __syncthreads();
#pragma unroll
        for (int i = 0; i < 6; ++i) wbs[tid + i * 256] = wreg[i];
        if (kk + 1 < 8) {
            const uint2* gn = (const uint2*)(g_Wa + (kk + 1) * W_CHUNK);
#pragma unroll
            for (int i = 0; i < 6; ++i) wreg[i] = __ldg(gn + tid + i * 256);
        }
        __syncthreads();
        mma_kstep(acc, A, WB, mrow, nbase, gid, tig, kk * 8);
    }

    // ---- epilogue: relu(D2 + b_apply) -> out ----
#pragma unroll
    for (int t = 0; t < 8; ++t) {
        const int n0 = nbase + t * 8 + 2 * tig;
        const float2 ba = __ldg((const float2*)(b_apply + n0));
#pragma unroll
        for (int s = 0; s < 2; ++s) {
            const int r0 = base + mrow + s * 16 + gid;
            if (r0 < N_NODES) {
                float2 v;
                v.x = fmaxf(acc[s][t][0] + ba.x, 0.f);
                v.y = fmaxf(acc[s][t][1] + ba.y, 0.f);
                *(float2*)(out + (size_t)r0 * 128 + n0) = v;
            }
            const int r1 = r0 + 8;
            if (r1 < N_NODES) {
                float2 v;
                v.x = fmaxf(acc[s][t][2] + ba.x, 0.f);
                v.y = fmaxf(acc[s][t][3] + ba.y, 0.f);
                *(float2*)(out + (size_t)r1 * 128 + n0) = v;
            }
        }
    }
}

extern "C" void kernel_launch(void* const* d_in, const int* in_sizes, int n_in,
                              void* d_out, int out_size) {
    (void)in_sizes; (void)n_in; (void)out_size;
    const float* nfeats  = (const float*)d_in[0];
    const float* efeats  = (const float*)d_in[1];
    const float* W_msg   = (const float*)d_in[2];
    const float* b_msg   = (const float*)d_in[3];
    const float* W_apply = (const float*)d_in[4];
    const float* b_apply = (const float*)d_in[5];
    const int*   src_idx = (const int*)d_in[6];
    float* out = (float*)d_out;

    cudaFuncSetAttribute(sage_combined, cudaFuncAttributeMaxDynamicSharedMemorySize, SMEM_BYTES);

    prep_weights<<<128, 256>>>(W_msg, W_apply);
    sage_combined<<<2 * NTILES, TPB, SMEM_BYTES>>>(nfeats, efeats, b_msg, b_apply, src_idx, out);
}

// round 8
// speedup vs baseline: 1.3439x; 1.3439x over previous
#include <cuda_runtime.h>
#include <cuda_bf16.h>
#include <cstdint>

#define N_NODES 50000
#define N_PAD   50048                  // 391 * 128
#define TILE    128
#define NTILES  391
#define TPB     256

#define A_STRIDE 800                   // A1 row: 96 pairs (768B) + 32B pad (≡32 mod 128)
#define A_BYTES  (128 * A_STRIDE)      // 102400 per tile
#define W_STRIDE 96                    // W chunk row: 8 pairs (64B) + 32B pad (≡96 mod 128)
#define W_CHUNK  (128 * W_STRIDE)      // 12288
#define SMEM_BYTES (A_BYTES + W_CHUNK) // 114688 -> 2 CTAs/SM

// __device__ scratch (allocation-free rule)
__device__ __align__(16) unsigned char g_Wm[12 * W_CHUNK];              // msg W, k16 chunks
__device__ __align__(16) unsigned char g_Wa[16 * W_CHUNK];              // apply W, k16 chunks
__device__ __align__(16) unsigned char g_A1[(size_t)N_PAD * A_STRIDE];  // packed gather sums

__device__ __forceinline__ void add4(float4& a, const float4 b) {
    a.x += b.x; a.y += b.y; a.z += b.z; a.w += b.w;
}
__device__ __forceinline__ void pack2(float a, float b, uint32_t& hw, uint32_t& lw) {
    __nv_bfloat162 h = __floats2bfloat162_rn(a, b);
    hw = *reinterpret_cast<uint32_t*>(&h);
    float2 hf = __bfloat1622float2(h);
    __nv_bfloat162 l = __floats2bfloat162_rn(a - hf.x, b - hf.y);
    lw = *reinterpret_cast<uint32_t*>(&l);
}
__device__ __forceinline__ void mma_bf16(float c[4],
                                         uint32_t a0, uint32_t a1, uint32_t a2, uint32_t a3,
                                         uint32_t b0, uint32_t b1) {
    asm volatile(
        "mma.sync.aligned.m16n8k16.row.col.f32.bf16.bf16.f32 "
        "{%0,%1,%2,%3}, {%4,%5,%6,%7}, {%8,%9}, {%0,%1,%2,%3};"
        : "+f"(c[0]), "+f"(c[1]), "+f"(c[2]), "+f"(c[3])
        : "r"(a0), "r"(a1), "r"(a2), "r"(a3), "r"(b0), "r"(b1));
}

// ---- gather kernel; CTAs 0..127 also prep the weight images inline ----
__global__ void __launch_bounds__(TPB, 4)
gather_kernel(const float* __restrict__ nfeats, const float* __restrict__ efeats,
              const int* __restrict__ src_idx,
              const float* __restrict__ Wm, const float* __restrict__ Wa) {
    const int tid  = threadIdx.x;
    const int wid  = tid >> 5;
    const int lane = tid & 31;

    // inline weight prep (one element per thread, first 128 CTAs)
    if (blockIdx.x < 128) {
        const int i = blockIdx.x * TPB + tid;   // 0..32767
        const int o = i >> 8, k = i & 255;
        {
            float w = Wa[o * 256 + k];
            __nv_bfloat16 h = __float2bfloat16(w);
            __nv_bfloat16 l = __float2bfloat16(w - __bfloat162float(h));
            unsigned char* p = g_Wa + (k >> 4) * W_CHUNK + o * W_STRIDE + ((k >> 1) & 7) * 8 + (k & 1) * 2;
            *(__nv_bfloat16*)p = h;
            *(__nv_bfloat16*)(p + 4) = l;
        }
        if (k < 192) {
            float w = Wm[o * 192 + k];
            __nv_bfloat16 h = __float2bfloat16(w);
            __nv_bfloat16 l = __float2bfloat16(w - __bfloat162float(h));
            unsigned char* p = g_Wm + (k >> 4) * W_CHUNK + o * W_STRIDE + ((k >> 1) & 7) * 8 + (k & 1) * 2;
            *(__nv_bfloat16*)p = h;
            *(__nv_bfloat16*)(p + 4) = l;
        }
    }

    const float4* nf4 = (const float4*)nfeats;
    const float4* ef4 = (const float4*)efeats;
    const int nd0 = blockIdx.x * 32 + wid * 4;
#pragma unroll
    for (int q = 0; q < 4; ++q) {
        const int node = nd0 + q;
        const int nc = node < N_NODES ? node : N_NODES - 1;   // clamp: uniform flow
        const int myidx = __ldg(src_idx + nc * 16 + (lane & 15));
        float4 a0 = {0,0,0,0}, a1 = {0,0,0,0}, e0 = {0,0,0,0}, e1 = {0,0,0,0};
#pragma unroll
        for (int j = 0; j < 16; j += 4) {
            const int s0 = __shfl_sync(0xffffffffu, myidx, j);
            const int s1 = __shfl_sync(0xffffffffu, myidx, j + 1);
            const int s2 = __shfl_sync(0xffffffffu, myidx, j + 2);
            const int s3 = __shfl_sync(0xffffffffu, myidx, j + 3);
            float4 n0 = __ldg(nf4 + (size_t)s0 * 32 + lane);
            float4 n1 = __ldg(nf4 + (size_t)s1 * 32 + lane);
            float4 n2 = __ldg(nf4 + (size_t)s2 * 32 + lane);
            float4 n3 = __ldg(nf4 + (size_t)s3 * 32 + lane);
            float4 f0 = __ldg(ef4 + ((size_t)nc * 16 + j + (lane >> 4)) * 16 + (lane & 15));
            float4 f1 = __ldg(ef4 + ((size_t)nc * 16 + j + 2 + (lane >> 4)) * 16 + (lane & 15));
            add4(a0, n0); add4(a1, n1); add4(a0, n2); add4(a1, n3);
            add4(e0, f0); add4(e1, f1);
        }
        add4(a0, a1);
        add4(e0, e1);
        e0.x += __shfl_down_sync(0xffffffffu, e0.x, 16);
        e0.y += __shfl_down_sync(0xffffffffu, e0.y, 16);
        e0.z += __shfl_down_sync(0xffffffffu, e0.z, 16);
        e0.w += __shfl_down_sync(0xffffffffu, e0.w, 16);
        if (node < N_NODES) {
            const float inv = 0.0625f;   // mean: exactly 16 in-edges per node
            unsigned char* ar = g_A1 + (size_t)node * A_STRIDE;
            uint32_t h0, l0, h1, l1;
            pack2(a0.x * inv, a0.y * inv, h0, l0);
            pack2(a0.z * inv, a0.w * inv, h1, l1);
            *(uint4*)(ar + lane * 16) = make_uint4(h0, l0, h1, l1);
            if (lane < 16) {
                pack2(e0.x * inv, e0.y * inv, h0, l0);
                pack2(e0.z * inv, e0.w * inv, h1, l1);
                *(uint4*)(ar + 512 + lane * 16) = make_uint4(h0, l0, h1, l1);
            }
        }
    }
}

// One k16-step of the split-bf16 GEMM: warp tile m32 x n64, 48 HMMAs.
__device__ __forceinline__ void mma_kstep(float acc[2][8][4], const char* __restrict__ A,
                                          const char* __restrict__ WB,
                                          int mrow, int nbase, int gid, int tig, int kb) {
    uint2 a[2][4];
#pragma unroll
    for (int s = 0; s < 2; ++s) {
        const char* ar = A + (mrow + s * 16 + gid) * A_STRIDE;
        a[s][0] = *(const uint2*)(ar + (kb + tig) * 8);
        a[s][1] = *(const uint2*)(ar + 8 * A_STRIDE + (kb + tig) * 8);
        a[s][2] = *(const uint2*)(ar + (kb + 4 + tig) * 8);
        a[s][3] = *(const uint2*)(ar + 8 * A_STRIDE + (kb + 4 + tig) * 8);
    }
#pragma unroll
    for (int t = 0; t < 8; ++t) {
        const char* wr = WB + (nbase + t * 8 + gid) * W_STRIDE + tig * 8;
        uint2 B0 = *(const uint2*)(wr);
        uint2 B1 = *(const uint2*)(wr + 32);
#pragma unroll
        for (int s = 0; s < 2; ++s) {
            mma_bf16(acc[s][t], a[s][0].x, a[s][1].x, a[s][2].x, a[s][3].x, B0.x, B1.x);  // hi*hi
            mma_bf16(acc[s][t], a[s][0].x, a[s][1].x, a[s][2].x, a[s][3].x, B0.y, B1.y);  // hi*lo
            mma_bf16(acc[s][t], a[s][0].y, a[s][1].y, a[s][2].y, a[s][3].y, B0.x, B1.x);  // lo*hi
        }
    }
}

__global__ void __launch_bounds__(TPB, 2)
gemm_kernel(const float* __restrict__ nfeats,
            const float* __restrict__ b_msg, const float* __restrict__ b_apply,
            float* __restrict__ out)
{
    extern __shared__ char sm[];
    char* A  = sm;
    char* WB = sm + A_BYTES;
    const int tid  = threadIdx.x;
    const int wid  = tid >> 5;
    const int lane = tid & 31;
    const int gid  = lane >> 2;
    const int tig  = lane & 3;
    const int mrow  = (wid & 3) * 32;
    const int nbase = (wid >> 2) * 64;
    const int base  = blockIdx.x * TILE;

    // prefetch W_msg chunk 0
    uint2 wreg[6];
    uint2* wbs = (uint2*)WB;
    {
        const uint2* g0 = (const uint2*)g_Wm;
#pragma unroll
        for (int i = 0; i < 6; ++i) wreg[i] = __ldg(g0 + tid + i * 256);
    }

    // ---- stage A1 tile: linear copy (102,400 B) ----
    {
        const float4* s = (const float4*)(g_A1 + (size_t)blockIdx.x * A_BYTES);
        float4* d = (float4*)A;
#pragma unroll
        for (int i = 0; i < 25; ++i) d[tid + i * TPB] = s[tid + i * TPB];
    }

    float acc[2][8][4];
#pragma unroll
    for (int s = 0; s < 2; ++s)
#pragma unroll
        for (int t = 0; t < 8; ++t)
#pragma unroll
            for (int j = 0; j < 4; ++j) acc[s][t][j] = 0.f;

    // ---- GEMM1: K=192, chunks 0..11 of g_Wm ----
    for (int kk = 0; kk < 12; ++kk) {
        __syncthreads();
#pragma unroll
        for (int i = 0; i < 6; ++i) wbs[tid + i * 256] = wreg[i];
        if (kk + 1 < 12) {
            const uint2* gn = (const uint2*)(g_Wm + (kk + 1) * W_CHUNK);
#pragma unroll
            for (int i = 0; i < 6; ++i) wreg[i] = __ldg(gn + tid + i * 256);
        }
        __syncthreads();
        mma_kstep(acc, A, WB, mrow, nbase, gid, tig, kk * 8);
    }

    // prefetch W_apply chunk 8 (h-half) while writing h back
    {
        const uint2* gn = (const uint2*)(g_Wa + 8 * W_CHUNK);
#pragma unroll
        for (int i = 0; i < 6; ++i) wreg[i] = __ldg(gn + tid + i * 256);
    }
    // h = D1 + b_msg -> A pairs [0,64). Safe: last kstep reads pairs 88..95 only.
#pragma unroll
    for (int t = 0; t < 8; ++t) {
        const int n0 = nbase + t * 8 + 2 * tig;
        const float2 bm = __ldg((const float2*)(b_msg + n0));
#pragma unroll
        for (int s = 0; s < 2; ++s) {
            char* ar = A + (mrow + s * 16 + gid) * A_STRIDE;
            uint32_t hw, lw;
            pack2(acc[s][t][0] + bm.x, acc[s][t][1] + bm.y, hw, lw);
            *(uint2*)(ar + (n0 >> 1) * 8) = make_uint2(hw, lw);
            pack2(acc[s][t][2] + bm.x, acc[s][t][3] + bm.y, hw, lw);
            *(uint2*)(ar + 8 * A_STRIDE + (n0 >> 1) * 8) = make_uint2(hw, lw);
        }
    }
#pragma unroll
    for (int s = 0; s < 2; ++s)
#pragma unroll
        for (int t = 0; t < 8; ++t)
#pragma unroll
            for (int j = 0; j < 4; ++j) acc[s][t][j] = 0.f;

    // ---- GEMM2a: h x W_apply[:,128:256] (chunks 8..15) ----
    for (int kk = 0; kk < 8; ++kk) {
        __syncthreads();
#pragma unroll
        for (int i = 0; i < 6; ++i) wbs[tid + i * 256] = wreg[i];
        if (kk + 1 < 8) {
            const uint2* gn = (const uint2*)(g_Wa + (9 + kk) * W_CHUNK);
#pragma unroll
            for (int i = 0; i < 6; ++i) wreg[i] = __ldg(gn + tid + i * 256);
        }
        __syncthreads();
        mma_kstep(acc, A, WB, mrow, nbase, gid, tig, kk * 8);
    }

    // prefetch W_apply chunk 0
    {
        const uint2* gn = (const uint2*)(g_Wa);
#pragma unroll
        for (int i = 0; i < 6; ++i) wreg[i] = __ldg(gn + tid + i * 256);
    }
    __syncthreads();    // all GEMM2a reads of A done before restage

    // ---- restage own-feature rows directly from nfeats (linear), pack bf16 hi/lo ----
    {
        const float4* s = (const float4*)(nfeats + (size_t)base * 128);
#pragma unroll
        for (int i = 0; i < 16; ++i) {
            const int idx = tid + i * TPB;          // 4096 float4 = 128 rows x 32
            const int row = idx >> 5, col = idx & 31;
            float4 v = {0,0,0,0};
            if (base + row < N_NODES) v = __ldg(s + idx);
            uint32_t h0, l0, h1, l1;
            pack2(v.x, v.y, h0, l0);
            pack2(v.z, v.w, h1, l1);
            char* ar = A + row * A_STRIDE;
            *(uint2*)(ar + (col * 2) * 8)     = make_uint2(h0, l0);
            *(uint2*)(ar + (col * 2 + 1) * 8) = make_uint2(h1, l1);
        }
    }

    // ---- GEMM2b: nfeats x W_apply[:,0:128] (chunks 0..7), accumulate ----
    for (int kk = 0; kk < 8; ++kk) {
        __syncthreads();
#pragma unroll
        for (int i = 0; i < 6; ++i) wbs[tid + i * 256] = wreg[i];
        if (kk + 1 < 8) {
            const uint2* gn = (const uint2*)(g_Wa + (kk + 1) * W_CHUNK);
#pragma unroll
            for (int i = 0; i < 6; ++i) wreg[i] = __ldg(gn + tid + i * 256);
        }
        __syncthreads();
        mma_kstep(acc, A, WB, mrow, nbase, gid, tig, kk * 8);
    }

    // ---- epilogue: relu(D2 + b_apply) -> out ----
#pragma unroll
    for (int t = 0; t < 8; ++t) {
        const int n0 = nbase + t * 8 + 2 * tig;
        const float2 ba = __ldg((const float2*)(b_apply + n0));
#pragma unroll
        for (int s = 0; s < 2; ++s) {
            const int r0 = base + mrow + s * 16 + gid;
            if (r0 < N_NODES) {
                float2 v;
                v.x = fmaxf(acc[s][t][0] + ba.x, 0.f);
                v.y = fmaxf(acc[s][t][1] + ba.y, 0.f);
                *(float2*)(out + (size_t)r0 * 128 + n0) = v;
            }
            const int r1 = r0 + 8;
            if (r1 < N_NODES) {
                float2 v;
                v.x = fmaxf(acc[s][t][2] + ba.x, 0.f);
                v.y = fmaxf(acc[s][t][3] + ba.y, 0.f);
                *(float2*)(out + (size_t)r1 * 128 + n0) = v;
            }
        }
    }
}

extern "C" void kernel_launch(void* const* d_in, const int* in_sizes, int n_in,
                              void* d_out, int out_size) {
    (void)in_sizes; (void)n_in; (void)out_size;
    const float* nfeats  = (const float*)d_in[0];
    const float* efeats  = (const float*)d_in[1];
    const float* W_msg   = (const float*)d_in[2];
    const float* b_msg   = (const float*)d_in[3];
    const float* W_apply = (const float*)d_in[4];
    const float* b_apply = (const float*)d_in[5];
    const int*   src_idx = (const int*)d_in[6];
    float* out = (float*)d_out;

    cudaFuncSetAttribute(gemm_kernel, cudaFuncAttributeMaxDynamicSharedMemorySize, SMEM_BYTES);

    gather_kernel<<<(N_NODES + 31) / 32, TPB>>>(nfeats, efeats, src_idx, W_msg, W_apply);
    gemm_kernel<<<NTILES, TPB, SMEM_BYTES>>>(nfeats, b_msg, b_apply, out);
}

// round 9
// speedup vs baseline: 1.4585x; 1.0853x over previous
#include <cuda_runtime.h>
#include <cuda_bf16.h>
#include <cstdint>

#define N_NODES 50000
#define N_PAD   50048
#define TPB     256

// gather side (unchanged layout)
#define A_STRIDE 800                   // packed A1 row: 96 pairs (768B) + 32B pad
// gemm side
#define TILE_M   64
#define NTILES   782                   // 782 * 64 = 50048
#define A_BYTES  (TILE_M * A_STRIDE)   // 51200 smem per CTA -> 3 CTAs/SM (reg-capped)

// W fragment records: [kstep][nblock(16)][lane(32)] x 16B; lane record = {hi0,lo0,hi1,lo1}
__device__ __align__(16) unsigned char g_Wm[12 * 16 * 512];   // 98304
__device__ __align__(16) unsigned char g_Wa[16 * 16 * 512];   // 131072
__device__ __align__(16) unsigned char g_A1[(size_t)N_PAD * A_STRIDE];

__device__ __forceinline__ void add4(float4& a, const float4 b) {
    a.x += b.x; a.y += b.y; a.z += b.z; a.w += b.w;
}
__device__ __forceinline__ void pack2(float a, float b, uint32_t& hw, uint32_t& lw) {
    __nv_bfloat162 h = __floats2bfloat162_rn(a, b);
    hw = *reinterpret_cast<uint32_t*>(&h);
    float2 hf = __bfloat1622float2(h);
    __nv_bfloat162 l = __floats2bfloat162_rn(a - hf.x, b - hf.y);
    lw = *reinterpret_cast<uint32_t*>(&l);
}
__device__ __forceinline__ void mma_bf16(float c[4],
                                         uint32_t a0, uint32_t a1, uint32_t a2, uint32_t a3,
                                         uint32_t b0, uint32_t b1) {
    asm volatile(
        "mma.sync.aligned.m16n8k16.row.col.f32.bf16.bf16.f32 "
        "{%0,%1,%2,%3}, {%4,%5,%6,%7}, {%8,%9}, {%0,%1,%2,%3};"
        : "+f"(c[0]), "+f"(c[1]), "+f"(c[2]), "+f"(c[3])
        : "r"(a0), "r"(a1), "r"(a2), "r"(a3), "r"(b0), "r"(b1));
}

// write one W element into fragment-record layout
__device__ __forceinline__ void store_w(unsigned char* base, int o, int k,
                                        __nv_bfloat16 h, __nv_bfloat16 l) {
    const int kk = k >> 4, r = k & 15;
    const int gid = o & 7, nblock = o >> 3;
    const int tig = (r & 7) >> 1;
    const int word_off = r & 8;          // 0 (B0) or 8 (B1)
    const int halfsel = r & 1;
    unsigned char* p = base + ((size_t)(kk * 16 + nblock) * 32 + gid * 4 + tig) * 16;
    *(__nv_bfloat16*)(p + word_off + halfsel * 2)     = h;   // hi word
    *(__nv_bfloat16*)(p + word_off + 4 + halfsel * 2) = l;   // lo word
}

// ---- gather kernel; CTAs 0..127 also prep the weight images inline ----
__global__ void __launch_bounds__(TPB, 4)
gather_kernel(const float* __restrict__ nfeats, const float* __restrict__ efeats,
              const int* __restrict__ src_idx,
              const float* __restrict__ Wm, const float* __restrict__ Wa) {
    const int tid  = threadIdx.x;
    const int wid  = tid >> 5;
    const int lane = tid & 31;

    if (blockIdx.x < 128) {
        const int i = blockIdx.x * TPB + tid;   // 0..32767
        const int o = i >> 8, k = i & 255;
        {
            float w = Wa[o * 256 + k];
            __nv_bfloat16 h = __float2bfloat16(w);
            __nv_bfloat16 l = __float2bfloat16(w - __bfloat162float(h));
            store_w(g_Wa, o, k, h, l);
        }
        if (k < 192) {
            float w = Wm[o * 192 + k];
            __nv_bfloat16 h = __float2bfloat16(w);
            __nv_bfloat16 l = __float2bfloat16(w - __bfloat162float(h));
            store_w(g_Wm, o, k, h, l);
        }
    }

    const float4* nf4 = (const float4*)nfeats;
    const float4* ef4 = (const float4*)efeats;
    const int nd0 = blockIdx.x * 32 + wid * 4;
#pragma unroll
    for (int q = 0; q < 4; ++q) {
        const int node = nd0 + q;
        const int nc = node < N_NODES ? node : N_NODES - 1;
        const int myidx = __ldg(src_idx + nc * 16 + (lane & 15));
        float4 a0 = {0,0,0,0}, a1 = {0,0,0,0}, e0 = {0,0,0,0}, e1 = {0,0,0,0};
#pragma unroll
        for (int j = 0; j < 16; j += 4) {
            const int s0 = __shfl_sync(0xffffffffu, myidx, j);
            const int s1 = __shfl_sync(0xffffffffu, myidx, j + 1);
            const int s2 = __shfl_sync(0xffffffffu, myidx, j + 2);
            const int s3 = __shfl_sync(0xffffffffu, myidx, j + 3);
            float4 n0 = __ldg(nf4 + (size_t)s0 * 32 + lane);
            float4 n1 = __ldg(nf4 + (size_t)s1 * 32 + lane);
            float4 n2 = __ldg(nf4 + (size_t)s2 * 32 + lane);
            float4 n3 = __ldg(nf4 + (size_t)s3 * 32 + lane);
            float4 f0 = __ldg(ef4 + ((size_t)nc * 16 + j + (lane >> 4)) * 16 + (lane & 15));
            float4 f1 = __ldg(ef4 + ((size_t)nc * 16 + j + 2 + (lane >> 4)) * 16 + (lane & 15));
            add4(a0, n0); add4(a1, n1); add4(a0, n2); add4(a1, n3);
            add4(e0, f0); add4(e1, f1);
        }
        add4(a0, a1);
        add4(e0, e1);
        e0.x += __shfl_down_sync(0xffffffffu, e0.x, 16);
        e0.y += __shfl_down_sync(0xffffffffu, e0.y, 16);
        e0.z += __shfl_down_sync(0xffffffffu, e0.z, 16);
        e0.w += __shfl_down_sync(0xffffffffu, e0.w, 16);
        if (node < N_NODES) {
            const float inv = 0.0625f;   // mean: exactly 16 in-edges per node
            unsigned char* ar = g_A1 + (size_t)node * A_STRIDE;
            uint32_t h0, l0, h1, l1;
            pack2(a0.x * inv, a0.y * inv, h0, l0);
            pack2(a0.z * inv, a0.w * inv, h1, l1);
            *(uint4*)(ar + lane * 16) = make_uint4(h0, l0, h1, l1);
            if (lane < 16) {
                pack2(e0.x * inv, e0.y * inv, h0, l0);
                pack2(e0.z * inv, e0.w * inv, h1, l1);
                *(uint4*)(ar + 512 + lane * 16) = make_uint4(h0, l0, h1, l1);
            }
        }
    }
}

// One barrier-free k16 step: A frags from smem, B frag = 1 LDG.128/lane (L1-resident).
__device__ __forceinline__ void mma_kstep(float acc[2][4][4], const char* __restrict__ A,
                                          const uint4* __restrict__ wrec,
                                          int mrow, int nb, int gid, int tig, int lane,
                                          int kk_rec, int kb) {
    uint2 a[2][4];
#pragma unroll
    for (int s = 0; s < 2; ++s) {
        const char* ar = A + (mrow + s * 16 + gid) * A_STRIDE;
        a[s][0] = *(const uint2*)(ar + (kb + tig) * 8);
        a[s][1] = *(const uint2*)(ar + 8 * A_STRIDE + (kb + tig) * 8);
        a[s][2] = *(const uint2*)(ar + (kb + 4 + tig) * 8);
        a[s][3] = *(const uint2*)(ar + 8 * A_STRIDE + (kb + 4 + tig) * 8);
    }
#pragma unroll
    for (int t = 0; t < 4; ++t) {
        const uint4 B = __ldg(wrec + (size_t)(kk_rec * 16 + nb + t) * 32 + lane);
#pragma unroll
        for (int s = 0; s < 2; ++s) {
            mma_bf16(acc[s][t], a[s][0].x, a[s][1].x, a[s][2].x, a[s][3].x, B.x, B.z);  // hi*hi
            mma_bf16(acc[s][t], a[s][0].x, a[s][1].x, a[s][2].x, a[s][3].x, B.y, B.w);  // hi*lo
            mma_bf16(acc[s][t], a[s][0].y, a[s][1].y, a[s][2].y, a[s][3].y, B.x, B.z);  // lo*hi
        }
    }
}

__global__ void __launch_bounds__(TPB, 3)
gemm_kernel(const float* __restrict__ nfeats,
            const float* __restrict__ b_msg, const float* __restrict__ b_apply,
            float* __restrict__ out)
{
    extern __shared__ char A[];
    const int tid  = threadIdx.x;
    const int wid  = tid >> 5;
    const int lane = tid & 31;
    const int gid  = lane >> 2;
    const int tig  = lane & 3;
    const int mrow = (wid >> 2) * 32;    // 0 / 32
    const int nb   = (wid & 3) * 4;      // n8-block base 0/4/8/12
    const int base = blockIdx.x * TILE_M;

    // ---- stage A1 tile: linear copy (51,200 B) ----
    {
        const float4* s = (const float4*)(g_A1 + (size_t)blockIdx.x * A_BYTES);
        float4* d = (float4*)A;
#pragma unroll
        for (int i = 0; i < 13; ++i) {
            const int idx = tid + i * TPB;
            if (idx < A_BYTES / 16) d[idx] = s[idx];
        }
    }
    __syncthreads();

    float acc[2][4][4];
#pragma unroll
    for (int s = 0; s < 2; ++s)
#pragma unroll
        for (int t = 0; t < 4; ++t)
#pragma unroll
            for (int j = 0; j < 4; ++j) acc[s][t][j] = 0.f;

    // ---- GEMM1: K=192, barrier-free ----
    const uint4* wm = (const uint4*)g_Wm;
#pragma unroll
    for (int kk = 0; kk < 12; ++kk)
        mma_kstep(acc, A, wm, mrow, nb, gid, tig, lane, kk, kk * 8);
    __syncthreads();   // all GEMM1 A-reads done before h writeback

    // ---- h = D1 + b_msg -> A pairs [0,64) ----
#pragma unroll
    for (int t = 0; t < 4; ++t) {
        const int n0 = (wid & 3) * 32 + t * 8 + 2 * tig;
        const float2 bm = __ldg((const float2*)(b_msg + n0));
#pragma unroll
        for (int s = 0; s < 2; ++s) {
            char* ar = A + (mrow + s * 16 + gid) * A_STRIDE;
            uint32_t hw, lw;
            pack2(acc[s][t][0] + bm.x, acc[s][t][1] + bm.y, hw, lw);
            *(uint2*)(ar + (n0 >> 1) * 8) = make_uint2(hw, lw);
            pack2(acc[s][t][2] + bm.x, acc[s][t][3] + bm.y, hw, lw);
            *(uint2*)(ar + 8 * A_STRIDE + (n0 >> 1) * 8) = make_uint2(hw, lw);
        }
    }
    __syncthreads();   // h visible to all warps

#pragma unroll
    for (int s = 0; s < 2; ++s)
#pragma unroll
        for (int t = 0; t < 4; ++t)
#pragma unroll
            for (int j = 0; j < 4; ++j) acc[s][t][j] = 0.f;

    // ---- GEMM2a: h x W_apply[:,128:256] (records 8..15), barrier-free ----
    const uint4* wa = (const uint4*)g_Wa;
#pragma unroll
    for (int kk = 0; kk < 8; ++kk)
        mma_kstep(acc, A, wa, mrow, nb, gid, tig, lane, kk + 8, kk * 8);
    __syncthreads();   // all GEMM2a A-reads done before restage

    // ---- restage own-feature rows from nfeats (linear), pack bf16 hi/lo ----
    {
        const float4* s = (const float4*)(nfeats + (size_t)base * 128);
#pragma unroll
        for (int i = 0; i < 8; ++i) {
            const int idx = tid + i * TPB;          // 2048 float4 = 64 rows x 32
            const int row = idx >> 5, col = idx & 31;
            float4 v = {0,0,0,0};
            if (base + row < N_NODES) v = __ldg(s + idx);
            uint32_t h0, l0, h1, l1;
            pack2(v.x, v.y, h0, l0);
            pack2(v.z, v.w, h1, l1);
            char* ar = A + row * A_STRIDE;
            *(uint2*)(ar + (col * 2) * 8)     = make_uint2(h0, l0);
            *(uint2*)(ar + (col * 2 + 1) * 8) = make_uint2(h1, l1);
        }
    }
    __syncthreads();

    // ---- GEMM2b: nfeats x W_apply[:,0:128] (records 0..7), accumulate ----
#pragma unroll
    for (int kk = 0; kk < 8; ++kk)
        mma_kstep(acc, A, wa, mrow, nb, gid, tig, lane, kk, kk * 8);

    // ---- epilogue: relu(D2 + b_apply) -> out ----
#pragma unroll
    for (int t = 0; t < 4; ++t) {
        const int n0 = (wid & 3) * 32 + t * 8 + 2 * tig;
        const float2 ba = __ldg((const float2*)(b_apply + n0));
#pragma unroll
        for (int s = 0; s < 2; ++s) {
            const int r0 = base + mrow + s * 16 + gid;
            if (r0 < N_NODES) {
                float2 v;
                v.x = fmaxf(acc[s][t][0] + ba.x, 0.f);
                v.y = fmaxf(acc[s][t][1] + ba.y, 0.f);
                *(float2*)(out + (size_t)r0 * 128 + n0) = v;
            }
            const int r1 = r0 + 8;
            if (r1 < N_NODES) {
                float2 v;
                v.x = fmaxf(acc[s][t][2] + ba.x, 0.f);
                v.y = fmaxf(acc[s][t][3] + ba.y, 0.f);
                *(float2*)(out + (size_t)r1 * 128 + n0) = v;
            }
        }
    }
}

extern "C" void kernel_launch(void* const* d_in, const int* in_sizes, int n_in,
                              void* d_out, int out_size) {
    (void)in_sizes; (void)n_in; (void)out_size;
    const float* nfeats  = (const float*)d_in[0];
    const float* efeats  = (const float*)d_in[1];
    const float* W_msg   = (const float*)d_in[2];
    const float* b_msg   = (const float*)d_in[3];
    const float* W_apply = (const float*)d_in[4];
    const float* b_apply = (const float*)d_in[5];
    const int*   src_idx = (const int*)d_in[6];
    float* out = (float*)d_out;

    cudaFuncSetAttribute(gemm_kernel, cudaFuncAttributeMaxDynamicSharedMemorySize, A_BYTES);

    gather_kernel<<<(N_NODES + 31) / 32, TPB>>>(nfeats, efeats, src_idx, W_msg, W_apply);
    gemm_kernel<<<NTILES, TPB, A_BYTES>>>(nfeats, b_msg, b_apply, out);
}

// round 10
// speedup vs baseline: 1.6185x; 1.1096x over previous
#include <cuda_runtime.h>
#include <cuda_bf16.h>
#include <cstdint>

#define N_NODES 50000
#define TPB     256
#define TILE_M  64
#define NTILES  782                    // 782 * 64 = 50048
#define A_STRIDE 800                   // packed A row: 96 pairs (768B) + 32B pad
#define A_BYTES  (TILE_M * A_STRIDE)   // 51200 smem -> 3 CTAs/SM

// W fragment records: [kstep][nblock(16)][lane(32)] x 16B; lane record = {hi0,lo0,hi1,lo1}
__device__ __align__(16) unsigned char g_Wm[12 * 16 * 512];   // 98304
__device__ __align__(16) unsigned char g_Wa[16 * 16 * 512];   // 131072

__device__ __forceinline__ void add4(float4& a, const float4 b) {
    a.x += b.x; a.y += b.y; a.z += b.z; a.w += b.w;
}
__device__ __forceinline__ void pack2(float a, float b, uint32_t& hw, uint32_t& lw) {
    __nv_bfloat162 h = __floats2bfloat162_rn(a, b);
    hw = *reinterpret_cast<uint32_t*>(&h);
    float2 hf = __bfloat1622float2(h);
    __nv_bfloat162 l = __floats2bfloat162_rn(a - hf.x, b - hf.y);
    lw = *reinterpret_cast<uint32_t*>(&l);
}
__device__ __forceinline__ void mma_bf16(float c[4],
                                         uint32_t a0, uint32_t a1, uint32_t a2, uint32_t a3,
                                         uint32_t b0, uint32_t b1) {
    asm volatile(
        "mma.sync.aligned.m16n8k16.row.col.f32.bf16.bf16.f32 "
        "{%0,%1,%2,%3}, {%4,%5,%6,%7}, {%8,%9}, {%0,%1,%2,%3};"
        : "+f"(c[0]), "+f"(c[1]), "+f"(c[2]), "+f"(c[3])
        : "r"(a0), "r"(a1), "r"(a2), "r"(a3), "r"(b0), "r"(b1));
}

__device__ __forceinline__ void store_w(unsigned char* base, int o, int k,
                                        __nv_bfloat16 h, __nv_bfloat16 l) {
    const int kk = k >> 4, r = k & 15;
    const int gid = o & 7, nblock = o >> 3;
    const int tig = (r & 7) >> 1;
    const int word_off = r & 8;
    const int halfsel = r & 1;
    unsigned char* p = base + ((size_t)(kk * 16 + nblock) * 32 + gid * 4 + tig) * 16;
    *(__nv_bfloat16*)(p + word_off + halfsel * 2)     = h;
    *(__nv_bfloat16*)(p + word_off + 4 + halfsel * 2) = l;
}

// one-time: weights -> fragment-record hi/lo layout
__global__ void prep_weights(const float* __restrict__ Wm, const float* __restrict__ Wa) {
    const int i = blockIdx.x * blockDim.x + threadIdx.x;
    if (i >= 128 * 256) return;
    const int o = i >> 8, k = i & 255;
    {
        float w = Wa[o * 256 + k];
        __nv_bfloat16 h = __float2bfloat16(w);
        __nv_bfloat16 l = __float2bfloat16(w - __bfloat162float(h));
        store_w(g_Wa, o, k, h, l);
    }
    if (k < 192) {
        float w = Wm[o * 192 + k];
        __nv_bfloat16 h = __float2bfloat16(w);
        __nv_bfloat16 l = __float2bfloat16(w - __bfloat162float(h));
        store_w(g_Wm, o, k, h, l);
    }
}

// One barrier-free k16 step with hoisted pointers. ar0 = A row (mrow+gid), wp = B record ptr.
__device__ __forceinline__ void mma_kstep_p(float acc[2][4][4], const char* ar0,
                                            const uint4* wp, int koff) {
    uint2 a[2][4];
#pragma unroll
    for (int s = 0; s < 2; ++s) {
        const char* ar = ar0 + s * 16 * A_STRIDE + koff;
        a[s][0] = *(const uint2*)(ar);
        a[s][1] = *(const uint2*)(ar + 8 * A_STRIDE);
        a[s][2] = *(const uint2*)(ar + 32);
        a[s][3] = *(const uint2*)(ar + 8 * A_STRIDE + 32);
    }
#pragma unroll
    for (int t = 0; t < 4; ++t) {
        const uint4 B = __ldg(wp + t * 32);
#pragma unroll
        for (int s = 0; s < 2; ++s) {
            mma_bf16(acc[s][t], a[s][0].x, a[s][1].x, a[s][2].x, a[s][3].x, B.x, B.z);  // hi*hi
            mma_bf16(acc[s][t], a[s][0].x, a[s][1].x, a[s][2].x, a[s][3].x, B.y, B.w);  // hi*lo
            mma_bf16(acc[s][t], a[s][0].y, a[s][1].y, a[s][2].y, a[s][3].y, B.x, B.z);  // lo*hi
        }
    }
}

__global__ void __launch_bounds__(TPB, 3)
sage_fused(const float* __restrict__ nfeats, const float* __restrict__ efeats,
           const float* __restrict__ b_msg, const float* __restrict__ b_apply,
           const int* __restrict__ src_idx, float* __restrict__ out)
{
    extern __shared__ char A[];
    const int tid  = threadIdx.x;
    const int wid  = tid >> 5;
    const int lane = tid & 31;
    const int gid  = lane >> 2;
    const int tig  = lane & 3;
    const int mrow = (wid >> 2) * 32;    // 0 / 32
    const int nb   = (wid & 3) * 4;      // n8-block base
    const int base = blockIdx.x * TILE_M;

    // ---- gather phase: 8 nodes per warp, packed straight into smem A ----
    {
        const float4* nf4 = (const float4*)nfeats;
        const float4* ef4 = (const float4*)efeats;
#pragma unroll 2
        for (int q = 0; q < 8; ++q) {
            const int nd = wid * 8 + q;
            const int node = base + nd;
            if (node >= N_NODES) break;           // warp-uniform
            const int myidx = __ldg(src_idx + node * 16 + (lane & 15));
            float4 a0 = {0,0,0,0}, a1 = {0,0,0,0}, e0 = {0,0,0,0}, e1 = {0,0,0,0};
#pragma unroll
            for (int j = 0; j < 16; j += 4) {
                const int s0 = __shfl_sync(0xffffffffu, myidx, j);
                const int s1 = __shfl_sync(0xffffffffu, myidx, j + 1);
                const int s2 = __shfl_sync(0xffffffffu, myidx, j + 2);
                const int s3 = __shfl_sync(0xffffffffu, myidx, j + 3);
                float4 n0 = __ldg(nf4 + (size_t)s0 * 32 + lane);
                float4 n1 = __ldg(nf4 + (size_t)s1 * 32 + lane);
                float4 n2 = __ldg(nf4 + (size_t)s2 * 32 + lane);
                float4 n3 = __ldg(nf4 + (size_t)s3 * 32 + lane);
                float4 f0 = __ldg(ef4 + ((size_t)node * 16 + j + (lane >> 4)) * 16 + (lane & 15));
                float4 f1 = __ldg(ef4 + ((size_t)node * 16 + j + 2 + (lane >> 4)) * 16 + (lane & 15));
                add4(a0, n0); add4(a1, n1); add4(a0, n2); add4(a1, n3);
                add4(e0, f0); add4(e1, f1);
            }
            add4(a0, a1);
            add4(e0, e1);
            e0.x += __shfl_down_sync(0xffffffffu, e0.x, 16);
            e0.y += __shfl_down_sync(0xffffffffu, e0.y, 16);
            e0.z += __shfl_down_sync(0xffffffffu, e0.z, 16);
            e0.w += __shfl_down_sync(0xffffffffu, e0.w, 16);
            const float inv = 0.0625f;   // mean: exactly 16 in-edges per node
            char* ar = A + nd * A_STRIDE;
            uint32_t h0, l0, h1, l1;
            pack2(a0.x * inv, a0.y * inv, h0, l0);
            pack2(a0.z * inv, a0.w * inv, h1, l1);
            *(uint4*)(ar + lane * 16) = make_uint4(h0, l0, h1, l1);
            if (lane < 16) {
                pack2(e0.x * inv, e0.y * inv, h0, l0);
                pack2(e0.z * inv, e0.w * inv, h1, l1);
                *(uint4*)(ar + 512 + lane * 16) = make_uint4(h0, l0, h1, l1);
            }
        }
    }
    __syncthreads();

    float acc[2][4][4];
#pragma unroll
    for (int s = 0; s < 2; ++s)
#pragma unroll
        for (int t = 0; t < 4; ++t)
#pragma unroll
            for (int j = 0; j < 4; ++j) acc[s][t][j] = 0.f;

    const char* ar0 = A + (mrow + gid) * A_STRIDE + tig * 8;

    // ---- GEMM1: K=192, barrier-free (B via L1-resident LDG) ----
    {
        const uint4* wp = (const uint4*)g_Wm + (size_t)nb * 32 + lane;
#pragma unroll
        for (int kk = 0; kk < 12; ++kk) {
            mma_kstep_p(acc, ar0, wp, kk * 64);
            wp += 512;
        }
    }
    __syncthreads();   // all GEMM1 A-reads done before h writeback

    // ---- h = D1 + b_msg -> A pairs [0,64) ----
#pragma unroll
    for (int t = 0; t < 4; ++t) {
        const int n0 = (wid & 3) * 32 + t * 8 + 2 * tig;
        const float2 bm = __ldg((const float2*)(b_msg + n0));
#pragma unroll
        for (int s = 0; s < 2; ++s) {
            char* ar = A + (mrow + s * 16 + gid) * A_STRIDE;
            uint32_t hw, lw;
            pack2(acc[s][t][0] + bm.x, acc[s][t][1] + bm.y, hw, lw);
            *(uint2*)(ar + (n0 >> 1) * 8) = make_uint2(hw, lw);
            pack2(acc[s][t][2] + bm.x, acc[s][t][3] + bm.y, hw, lw);
            *(uint2*)(ar + 8 * A_STRIDE + (n0 >> 1) * 8) = make_uint2(hw, lw);
        }
    }
    __syncthreads();   // h visible to all warps

#pragma unroll
    for (int s = 0; s < 2; ++s)
#pragma unroll
        for (int t = 0; t < 4; ++t)
#pragma unroll
            for (int j = 0; j < 4; ++j) acc[s][t][j] = 0.f;

    // ---- GEMM2a: h x W_apply[:,128:256] (records 8..15) ----
    {
        const uint4* wp = (const uint4*)g_Wa + (size_t)(8 * 16 + nb) * 32 + lane;
#pragma unroll
        for (int kk = 0; kk < 8; ++kk) {
            mma_kstep_p(acc, ar0, wp, kk * 64);
            wp += 512;
        }
    }
    __syncthreads();   // all GEMM2a A-reads done before restage

    // ---- restage own-feature rows from nfeats (linear), pack bf16 hi/lo ----
    {
        const float4* s = (const float4*)(nfeats + (size_t)base * 128);
#pragma unroll
        for (int i = 0; i < 8; ++i) {
            const int idx = tid + i * TPB;          // 2048 float4 = 64 rows x 32
            const int row = idx >> 5, col = idx & 31;
            float4 v = {0,0,0,0};
            if (base + row < N_NODES) v = __ldg(s + idx);
            uint32_t h0, l0, h1, l1;
            pack2(v.x, v.y, h0, l0);
            pack2(v.z, v.w, h1, l1);
            char* ar = A + row * A_STRIDE;
            *(uint2*)(ar + (col * 2) * 8)     = make_uint2(h0, l0);
            *(uint2*)(ar + (col * 2 + 1) * 8) = make_uint2(h1, l1);
        }
    }
    __syncthreads();

    // ---- GEMM2b: nfeats x W_apply[:,0:128] (records 0..7), accumulate ----
    {
        const uint4* wp = (const uint4*)g_Wa + (size_t)nb * 32 + lane;
#pragma unroll
        for (int kk = 0; kk < 8; ++kk) {
            mma_kstep_p(acc, ar0, wp, kk * 64);
            wp += 512;
        }
    }

    // ---- epilogue: relu(D2 + b_apply) -> out ----
#pragma unroll
    for (int t = 0; t < 4; ++t) {
        const int n0 = (wid & 3) * 32 + t * 8 + 2 * tig;
        const float2 ba = __ldg((const float2*)(b_apply + n0));
#pragma unroll
        for (int s = 0; s < 2; ++s) {
            const int r0 = base + mrow + s * 16 + gid;
            if (r0 < N_NODES) {
                float2 v;
                v.x = fmaxf(acc[s][t][0] + ba.x, 0.f);
                v.y = fmaxf(acc[s][t][1] + ba.y, 0.f);
                *(float2*)(out + (size_t)r0 * 128 + n0) = v;
            }
            const int r1 = r0 + 8;
            if (r1 < N_NODES) {
                float2 v;
                v.x = fmaxf(acc[s][t][2] + ba.x, 0.f);
                v.y = fmaxf(acc[s][t][3] + ba.y, 0.f);
                *(float2*)(out + (size_t)r1 * 128 + n0) = v;
            }
        }
    }
}

extern "C" void kernel_launch(void* const* d_in, const int* in_sizes, int n_in,
                              void* d_out, int out_size) {
    (void)in_sizes; (void)n_in; (void)out_size;
    const float* nfeats  = (const float*)d_in[0];
    const float* efeats  = (const float*)d_in[1];
    const float* W_msg   = (const float*)d_in[2];
    const float* b_msg   = (const float*)d_in[3];
    const float* W_apply = (const float*)d_in[4];
    const float* b_apply = (const float*)d_in[5];
    const int*   src_idx = (const int*)d_in[6];
    float* out = (float*)d_out;

    cudaFuncSetAttribute(sage_fused, cudaFuncAttributeMaxDynamicSharedMemorySize, A_BYTES);

    prep_weights<<<128, 256>>>(W_msg, W_apply);
    sage_fused<<<NTILES, TPB, A_BYTES>>>(nfeats, efeats, b_msg, b_apply, src_idx, out);
}